// round 1
// baseline (speedup 1.0000x reference)
#include <cuda_runtime.h>
#include <cuda_bf16.h>
#include <math.h>

// Problem constants
#define BB 2
#define SS 2048
#define EE 1024
#define HH 16
#define DD 64
#define MM (BB * SS)   // 4096 rows for projection GEMMs

// ---------------- scratch (device globals; no allocations allowed) ----------
__device__ float g_qp[BB * SS * EE];   // Q projected, [B,S,E]
__device__ float g_kp[BB * SS * EE];   // K projected
__device__ float g_vp[BB * SS * EE];   // V projected
__device__ float g_at[BB * SS * EE];   // attention output (concat), [B,S,E]

// ---------------- SGEMM: C[M,N] = A[M,K] @ B[K,N] + bias[N] -----------------
// 128x128 block, 8-deep K tile, 8x8 per-thread microtile, 256 threads.
#define GM 128
#define GN 128
#define GK 8
#define TM 8
#define TN 8

__global__ __launch_bounds__(256, 2)
void sgemm_bias_kernel(const float* __restrict__ A,
                       const float* __restrict__ B,
                       const float* __restrict__ bias,
                       float* __restrict__ C,
                       int M, int N, int K)
{
    __shared__ float As[GK][GM];   // transposed A tile
    __shared__ float Bs[GK][GN];

    const int tid = threadIdx.x;
    const int tx = tid & 15;        // 0..15
    const int ty = tid >> 4;        // 0..15
    const int bm = blockIdx.y * GM;
    const int bn = blockIdx.x * GN;

    // A tile load mapping: 128 rows x 8 cols = 256 float4
    const int arow = tid >> 1;            // 0..127
    const int acol = (tid & 1) * 4;       // 0 or 4
    // B tile load mapping: 8 rows x 128 cols = 256 float4
    const int brow = tid >> 5;            // 0..7
    const int bcol = (tid & 31) * 4;      // 0..124

    float acc[TM][TN];
#pragma unroll
    for (int i = 0; i < TM; i++)
#pragma unroll
        for (int j = 0; j < TN; j++) acc[i][j] = 0.0f;

    for (int k0 = 0; k0 < K; k0 += GK) {
        float4 a4 = *(const float4*)&A[(size_t)(bm + arow) * K + k0 + acol];
        float4 b4 = *(const float4*)&B[(size_t)(k0 + brow) * N + bn + bcol];
        As[acol + 0][arow] = a4.x;
        As[acol + 1][arow] = a4.y;
        As[acol + 2][arow] = a4.z;
        As[acol + 3][arow] = a4.w;
        *(float4*)&Bs[brow][bcol] = b4;
        __syncthreads();

#pragma unroll
        for (int kk = 0; kk < GK; kk++) {
            float4 ra0 = *(float4*)&As[kk][ty * TM];
            float4 ra1 = *(float4*)&As[kk][ty * TM + 4];
            float4 rb0 = *(float4*)&Bs[kk][tx * TN];
            float4 rb1 = *(float4*)&Bs[kk][tx * TN + 4];
            float ra[TM] = {ra0.x, ra0.y, ra0.z, ra0.w, ra1.x, ra1.y, ra1.z, ra1.w};
            float rb[TN] = {rb0.x, rb0.y, rb0.z, rb0.w, rb1.x, rb1.y, rb1.z, rb1.w};
#pragma unroll
            for (int i = 0; i < TM; i++)
#pragma unroll
                for (int j = 0; j < TN; j++)
                    acc[i][j] = fmaf(ra[i], rb[j], acc[i][j]);
        }
        __syncthreads();
    }

    // epilogue with bias
#pragma unroll
    for (int i = 0; i < TM; i++) {
        const size_t row = (size_t)(bm + ty * TM + i);
        float4 o0, o1;
        const int c0 = bn + tx * TN;
        o0.x = acc[i][0] + bias[c0 + 0];
        o0.y = acc[i][1] + bias[c0 + 1];
        o0.z = acc[i][2] + bias[c0 + 2];
        o0.w = acc[i][3] + bias[c0 + 3];
        o1.x = acc[i][4] + bias[c0 + 4];
        o1.y = acc[i][5] + bias[c0 + 5];
        o1.z = acc[i][6] + bias[c0 + 6];
        o1.w = acc[i][7] + bias[c0 + 7];
        *(float4*)&C[row * N + c0] = o0;
        *(float4*)&C[row * N + c0 + 4] = o1;
    }
}

// ---------------- Flash attention (causal), fp32 ----------------------------
// Block: 256 threads as 16x16. Tile: BQ=64 queries x BK=64 keys, D=64.
// Grid: (S/64, H, B). Q,K,V read from [B,S,E] projected buffers (head split is
// pure indexing). Online softmax; P overwrites the K smem buffer.
#define BQ 64
#define BKT 64
#define KS_STRIDE 68   // padded to avoid bank conflicts, keeps 16B alignment
#define FLASH_SMEM_BYTES ((BQ * DD + BQ * KS_STRIDE + BKT * DD) * 4)

__global__ __launch_bounds__(256, 2)
void flash_attn_kernel(const float* __restrict__ Qp,
                       const float* __restrict__ Kp,
                       const float* __restrict__ Vp,
                       float* __restrict__ Out)
{
    extern __shared__ float sm[];
    float* Qs = sm;                       // [64][64]
    float* Ks = sm + BQ * DD;             // [64][68]  (later holds P)
    float* Vs = Ks + BQ * KS_STRIDE;      // [64][64]

    const int tid = threadIdx.x;
    const int tx = tid & 15;
    const int ty = tid >> 4;
    const int qt = blockIdx.x;
    const int h  = blockIdx.y;
    const int b  = blockIdx.z;
    const int qbase = qt * BQ;
    const size_t head_off = (size_t)h * DD;

    // load Q tile (pre-scaled by 1/sqrt(D))
    for (int i = tid; i < BQ * (DD / 4); i += 256) {
        int row = i >> 4;
        int c4 = (i & 15) * 4;
        float4 q4 = *(const float4*)&Qp[((size_t)(b * SS + qbase + row)) * EE + head_off + c4];
        q4.x *= 0.125f; q4.y *= 0.125f; q4.z *= 0.125f; q4.w *= 0.125f;
        *(float4*)&Qs[row * DD + c4] = q4;
    }

    float m_i[4], l_i[4];
    float accO[4][4];
#pragma unroll
    for (int i = 0; i < 4; i++) {
        m_i[i] = -1e30f;
        l_i[i] = 0.0f;
#pragma unroll
        for (int j = 0; j < 4; j++) accO[i][j] = 0.0f;
    }

    for (int kt = 0; kt <= qt; kt++) {
        const int kbase = kt * BKT;
        __syncthreads();  // previous iteration's P/V reads done before overwrite
        // load K, V tiles
        for (int i = tid; i < BKT * (DD / 4); i += 256) {
            int row = i >> 4;
            int c4 = (i & 15) * 4;
            float4 k4 = *(const float4*)&Kp[((size_t)(b * SS + kbase + row)) * EE + head_off + c4];
            *(float4*)&Ks[row * KS_STRIDE + c4] = k4;
            float4 v4 = *(const float4*)&Vp[((size_t)(b * SS + kbase + row)) * EE + head_off + c4];
            *(float4*)&Vs[row * DD + c4] = v4;
        }
        __syncthreads();

        // scores S = Qs @ Ks^T  (4x4 microtile)
        float s[4][4];
#pragma unroll
        for (int i = 0; i < 4; i++)
#pragma unroll
            for (int j = 0; j < 4; j++) s[i][j] = 0.0f;

#pragma unroll
        for (int d0 = 0; d0 < DD; d0 += 4) {
            float4 qv[4], kv[4];
#pragma unroll
            for (int i = 0; i < 4; i++) qv[i] = *(float4*)&Qs[(ty * 4 + i) * DD + d0];
#pragma unroll
            for (int j = 0; j < 4; j++) kv[j] = *(float4*)&Ks[(tx * 4 + j) * KS_STRIDE + d0];
#pragma unroll
            for (int i = 0; i < 4; i++)
#pragma unroll
                for (int j = 0; j < 4; j++) {
                    s[i][j] = fmaf(qv[i].x, kv[j].x, s[i][j]);
                    s[i][j] = fmaf(qv[i].y, kv[j].y, s[i][j]);
                    s[i][j] = fmaf(qv[i].z, kv[j].z, s[i][j]);
                    s[i][j] = fmaf(qv[i].w, kv[j].w, s[i][j]);
                }
        }

        // causal mask on diagonal tile
        if (kt == qt) {
#pragma unroll
            for (int i = 0; i < 4; i++) {
                const int qrow = ty * 4 + i;
#pragma unroll
                for (int j = 0; j < 4; j++) {
                    if (tx * 4 + j > qrow) s[i][j] = -1e30f;
                }
            }
        }

        // online softmax
        float alpha[4], ps[4], newm[4];
#pragma unroll
        for (int i = 0; i < 4; i++) {
            float mt = fmaxf(fmaxf(s[i][0], s[i][1]), fmaxf(s[i][2], s[i][3]));
#pragma unroll
            for (int off = 1; off < 16; off <<= 1)
                mt = fmaxf(mt, __shfl_xor_sync(0xffffffffu, mt, off));
            newm[i] = fmaxf(m_i[i], mt);
            alpha[i] = __expf(m_i[i] - newm[i]);
            float sum = 0.0f;
#pragma unroll
            for (int j = 0; j < 4; j++) {
                s[i][j] = __expf(s[i][j] - newm[i]);
                sum += s[i][j];
            }
#pragma unroll
            for (int off = 1; off < 16; off <<= 1)
                sum += __shfl_xor_sync(0xffffffffu, sum, off);
            ps[i] = sum;
        }

        __syncthreads();  // all K reads done before P overwrites Ks
        // write P into Ks buffer; rescale running state
#pragma unroll
        for (int i = 0; i < 4; i++) {
            m_i[i] = newm[i];
            l_i[i] = l_i[i] * alpha[i] + ps[i];
#pragma unroll
            for (int j = 0; j < 4; j++) accO[i][j] *= alpha[i];
            float4 p4 = make_float4(s[i][0], s[i][1], s[i][2], s[i][3]);
            *(float4*)&Ks[(ty * 4 + i) * KS_STRIDE + tx * 4] = p4;
        }
        __syncthreads();

        // O += P @ V
#pragma unroll
        for (int k0 = 0; k0 < BKT; k0 += 4) {
            float4 pv[4], vv[4];
#pragma unroll
            for (int i = 0; i < 4; i++) pv[i] = *(float4*)&Ks[(ty * 4 + i) * KS_STRIDE + k0];
#pragma unroll
            for (int kk = 0; kk < 4; kk++) vv[kk] = *(float4*)&Vs[(k0 + kk) * DD + tx * 4];
#pragma unroll
            for (int i = 0; i < 4; i++) {
                accO[i][0] = fmaf(pv[i].x, vv[0].x, accO[i][0]);
                accO[i][1] = fmaf(pv[i].x, vv[0].y, accO[i][1]);
                accO[i][2] = fmaf(pv[i].x, vv[0].z, accO[i][2]);
                accO[i][3] = fmaf(pv[i].x, vv[0].w, accO[i][3]);
                accO[i][0] = fmaf(pv[i].y, vv[1].x, accO[i][0]);
                accO[i][1] = fmaf(pv[i].y, vv[1].y, accO[i][1]);
                accO[i][2] = fmaf(pv[i].y, vv[1].z, accO[i][2]);
                accO[i][3] = fmaf(pv[i].y, vv[1].w, accO[i][3]);
                accO[i][0] = fmaf(pv[i].z, vv[2].x, accO[i][0]);
                accO[i][1] = fmaf(pv[i].z, vv[2].y, accO[i][1]);
                accO[i][2] = fmaf(pv[i].z, vv[2].z, accO[i][2]);
                accO[i][3] = fmaf(pv[i].z, vv[2].w, accO[i][3]);
                accO[i][0] = fmaf(pv[i].w, vv[3].x, accO[i][0]);
                accO[i][1] = fmaf(pv[i].w, vv[3].y, accO[i][1]);
                accO[i][2] = fmaf(pv[i].w, vv[3].z, accO[i][2]);
                accO[i][3] = fmaf(pv[i].w, vv[3].w, accO[i][3]);
            }
        }
    }

    // final normalize + store to [B,S,E]
#pragma unroll
    for (int i = 0; i < 4; i++) {
        const int qrow = qbase + ty * 4 + i;
        const float inv = 1.0f / l_i[i];
        float4 o = make_float4(accO[i][0] * inv, accO[i][1] * inv,
                               accO[i][2] * inv, accO[i][3] * inv);
        *(float4*)&Out[((size_t)(b * SS + qrow)) * EE + head_off + tx * 4] = o;
    }
}

// ---------------- launch ----------------------------------------------------
extern "C" void kernel_launch(void* const* d_in, const int* in_sizes, int n_in,
                              void* d_out, int out_size)
{
    const float* q  = (const float*)d_in[0];
    const float* k  = (const float*)d_in[1];
    const float* v  = (const float*)d_in[2];
    const float* Wq = (const float*)d_in[3];
    const float* bq = (const float*)d_in[4];
    const float* Wk = (const float*)d_in[5];
    const float* bk = (const float*)d_in[6];
    const float* Wv = (const float*)d_in[7];
    const float* bv = (const float*)d_in[8];
    const float* Wo = (const float*)d_in[9];
    const float* bo = (const float*)d_in[10];
    float* out = (float*)d_out;

    float* qp; cudaGetSymbolAddress((void**)&qp, g_qp);
    float* kp; cudaGetSymbolAddress((void**)&kp, g_kp);
    float* vp; cudaGetSymbolAddress((void**)&vp, g_vp);
    float* at; cudaGetSymbolAddress((void**)&at, g_at);

    cudaFuncSetAttribute(flash_attn_kernel,
                         cudaFuncAttributeMaxDynamicSharedMemorySize,
                         FLASH_SMEM_BYTES);

    dim3 gemm_grid(EE / GN, MM / GM);   // (8, 32)
    sgemm_bias_kernel<<<gemm_grid, 256>>>(q, Wq, bq, qp, MM, EE, EE);
    sgemm_bias_kernel<<<gemm_grid, 256>>>(k, Wk, bk, kp, MM, EE, EE);
    sgemm_bias_kernel<<<gemm_grid, 256>>>(v, Wv, bv, vp, MM, EE, EE);

    dim3 fa_grid(SS / BQ, HH, BB);      // (32, 16, 2)
    flash_attn_kernel<<<fa_grid, 256, FLASH_SMEM_BYTES>>>(qp, kp, vp, at);

    sgemm_bias_kernel<<<gemm_grid, 256>>>(at, Wo, bo, out, MM, EE, EE);
}

// round 5
// speedup vs baseline: 1.1466x; 1.1466x over previous
#include <cuda_runtime.h>
#include <cuda_bf16.h>
#include <math.h>
#include <stdint.h>

// Problem constants
#define BB 2
#define SS 2048
#define EE 1024
#define HH 16
#define DD 64
#define MM (BB * SS)   // 4096 rows for projection GEMMs

// ---------------- scratch (device globals; no allocations allowed) ----------
__device__ float g_qp[BB * SS * EE];   // Q projected, [B,S,E]
__device__ float g_kp[BB * SS * EE];   // K projected
__device__ float g_vp[BB * SS * EE];   // V projected
__device__ float g_at[BB * SS * EE];   // attention output (concat), [B,S,E]

// ======================= helpers ============================================
__device__ __forceinline__ uint32_t smem_u32(const void* p) {
    uint32_t a;
    asm("{ .reg .u64 t; cvta.to.shared.u64 t, %1; cvt.u32.u64 %0, t; }"
        : "=r"(a) : "l"(p));
    return a;
}
__device__ __forceinline__ void cp16(uint32_t dst, const void* src) {
    asm volatile("cp.async.cg.shared.global [%0], [%1], 16;" :: "r"(dst), "l"(src));
}
#define CP_COMMIT() asm volatile("cp.async.commit_group;" ::: "memory")
#define CP_WAIT0()  asm volatile("cp.async.wait_group 0;" ::: "memory")
#define CP_WAIT1()  asm volatile("cp.async.wait_group 1;" ::: "memory")

// tf32 round-to-nearest conversion (keeps value as f32 bits with low mantissa 0)
__device__ __forceinline__ uint32_t f2tf(float x) {
    uint32_t r;
    asm("cvt.rna.tf32.f32 %0, %1;" : "=r"(r) : "f"(x));
    return r;
}
// split x into hi (tf32) + lo (tf32 of residual)
__device__ __forceinline__ void tf32_split(float x, uint32_t& hi, uint32_t& lo) {
    hi = f2tf(x);
    lo = f2tf(x - __uint_as_float(hi));
}

__device__ __forceinline__ void mma_tf32(float* d, const uint32_t* a, const uint32_t* b) {
    asm volatile(
        "mma.sync.aligned.m16n8k8.row.col.f32.tf32.tf32.f32 "
        "{%0,%1,%2,%3}, {%4,%5,%6,%7}, {%8,%9}, {%0,%1,%2,%3};"
        : "+f"(d[0]), "+f"(d[1]), "+f"(d[2]), "+f"(d[3])
        : "r"(a[0]), "r"(a[1]), "r"(a[2]), "r"(a[3]), "r"(b[0]), "r"(b[1]));
}

// ======================= tf32 mma.sync GEMM =================================
// C[M,N=1024] = A[M,K=1024] @ W[K,N] + bias.  3xTF32 for fp32-level accuracy.
// CTA tile 128x128, K-chunk 32, 256 threads = 8 warps (2 M x 4 N), each warp
// 64x32 via 4x4 m16n8k8 tiles. 2-stage cp.async pipeline.
#define SA 36    // A smem row stride (floats): 32 + 4 pad
#define SB 132   // B smem row stride (floats): 128 + 4 pad
#define A_BUF_F (128 * SA)          // 4608 floats
#define B_BUF_F (32 * SB)           // 4224 floats
#define GEMM_SMEM_F (2 * A_BUF_F + 2 * B_BUF_F)
#define GEMM_SMEM_B (GEMM_SMEM_F * 4)   // 70656 bytes

__global__ __launch_bounds__(256, 1)
void gemm_tf32_mma(const float* __restrict__ A, const float* __restrict__ W,
                   const float* __restrict__ bias, float* __restrict__ C)
{
    extern __shared__ float smem[];
    float* As[2] = {smem, smem + A_BUF_F};
    float* Bs[2] = {smem + 2 * A_BUF_F, smem + 2 * A_BUF_F + B_BUF_F};
    const uint32_t sb0 = smem_u32(smem);

    const int tid = threadIdx.x;
    const int lane = tid & 31;
    const int wid = tid >> 5;
    const int warpM = wid >> 2;          // 0..1 -> 64 rows each
    const int warpN = wid & 3;           // 0..3 -> 32 cols each
    const int bm = blockIdx.y * 128;
    const int bn = blockIdx.x * 128;

    const int lg = lane >> 2;            // groupID 0..7
    const int lt = lane & 3;             // threadID_in_group 0..3

    float acc[4][4][4];
#pragma unroll
    for (int mi = 0; mi < 4; mi++)
#pragma unroll
        for (int ni = 0; ni < 4; ni++)
#pragma unroll
            for (int r = 0; r < 4; r++) acc[mi][ni][r] = 0.0f;

    // ---- tile loader: A chunk [128 x 32], W chunk [32 x 128]
    auto load_tiles = [&](int buf, int it) {
        const float* Ab = A + (size_t)bm * EE + it * 32;
        const float* Wb = W + (size_t)(it * 32) * EE + bn;
        const uint32_t sa = sb0 + (uint32_t)((As[buf] - smem) * 4);
        const uint32_t sw = sb0 + (uint32_t)((Bs[buf] - smem) * 4);
#pragma unroll
        for (int i = 0; i < 4; i++) {
            int cid = tid + i * 256;
            int row = cid >> 3, c4 = (cid & 7) * 4;
            cp16(sa + (uint32_t)(row * SA + c4) * 4, Ab + (size_t)row * EE + c4);
        }
#pragma unroll
        for (int i = 0; i < 4; i++) {
            int cid = tid + i * 256;
            int kk = cid >> 5, c4 = (cid & 31) * 4;
            cp16(sw + (uint32_t)(kk * SB + c4) * 4, Wb + (size_t)kk * EE + c4);
        }
    };

    load_tiles(0, 0); CP_COMMIT();
    load_tiles(1, 1); CP_COMMIT();

    for (int it = 0; it < 32; it++) {
        if (it == 31) { CP_WAIT0(); } else { CP_WAIT1(); }
        __syncthreads();

        const float* A_ = As[it & 1];
        const float* B_ = Bs[it & 1];

#pragma unroll
        for (int ks = 0; ks < 4; ks++) {
            const int kb = ks * 8;
            uint32_t ah[4][4], al[4][4];
#pragma unroll
            for (int mi = 0; mi < 4; mi++) {
                const int r0 = warpM * 64 + mi * 16 + lg;
                const int kk = kb + lt;
                tf32_split(A_[r0 * SA + kk],        ah[mi][0], al[mi][0]);
                tf32_split(A_[(r0 + 8) * SA + kk],  ah[mi][1], al[mi][1]);
                tf32_split(A_[r0 * SA + kk + 4],    ah[mi][2], al[mi][2]);
                tf32_split(A_[(r0 + 8) * SA + kk + 4], ah[mi][3], al[mi][3]);
            }
            uint32_t bh[4][2], bl[4][2];
#pragma unroll
            for (int ni = 0; ni < 4; ni++) {
                const int nn = warpN * 32 + ni * 8 + lg;
                const int kk = kb + lt;
                tf32_split(B_[kk * SB + nn],       bh[ni][0], bl[ni][0]);
                tf32_split(B_[(kk + 4) * SB + nn], bh[ni][1], bl[ni][1]);
            }
#pragma unroll
            for (int mi = 0; mi < 4; mi++)
#pragma unroll
                for (int ni = 0; ni < 4; ni++) {
                    mma_tf32(acc[mi][ni], ah[mi], bh[ni]);
                    mma_tf32(acc[mi][ni], al[mi], bh[ni]);
                    mma_tf32(acc[mi][ni], ah[mi], bl[ni]);
                }
        }
        __syncthreads();
        if (it + 2 < 32) { load_tiles(it & 1, it + 2); CP_COMMIT(); }
    }

    // ---- epilogue: bias + store (float2 per fragment pair)
#pragma unroll
    for (int mi = 0; mi < 4; mi++) {
        const int row0 = bm + warpM * 64 + mi * 16 + lg;
#pragma unroll
        for (int ni = 0; ni < 4; ni++) {
            const int col = bn + warpN * 32 + ni * 8 + lt * 2;
            const float b0 = bias[col], b1 = bias[col + 1];
            float2 v0 = make_float2(acc[mi][ni][0] + b0, acc[mi][ni][1] + b1);
            float2 v1 = make_float2(acc[mi][ni][2] + b0, acc[mi][ni][3] + b1);
            *(float2*)&C[(size_t)row0 * EE + col] = v0;
            *(float2*)&C[(size_t)(row0 + 8) * EE + col] = v1;
        }
    }
}

// ---------------- Flash attention (causal), fp32 (unchanged) ----------------
#define BQ 64
#define BKT 64
#define KS_STRIDE 68
#define FLASH_SMEM_BYTES ((BQ * DD + BQ * KS_STRIDE + BKT * DD) * 4)

__global__ __launch_bounds__(256, 2)
void flash_attn_kernel(const float* __restrict__ Qp,
                       const float* __restrict__ Kp,
                       const float* __restrict__ Vp,
                       float* __restrict__ Out)
{
    extern __shared__ float smf[];
    float* Qs = smf;
    float* Ks = smf + BQ * DD;
    float* Vs = Ks + BQ * KS_STRIDE;

    const int tid = threadIdx.x;
    const int tx = tid & 15;
    const int ty = tid >> 4;
    const int qt = blockIdx.x;
    const int h  = blockIdx.y;
    const int b  = blockIdx.z;
    const int qbase = qt * BQ;
    const size_t head_off = (size_t)h * DD;

    for (int i = tid; i < BQ * (DD / 4); i += 256) {
        int row = i >> 4;
        int c4 = (i & 15) * 4;
        float4 q4 = *(const float4*)&Qp[((size_t)(b * SS + qbase + row)) * EE + head_off + c4];
        q4.x *= 0.125f; q4.y *= 0.125f; q4.z *= 0.125f; q4.w *= 0.125f;
        *(float4*)&Qs[row * DD + c4] = q4;
    }

    float m_i[4], l_i[4];
    float accO[4][4];
#pragma unroll
    for (int i = 0; i < 4; i++) {
        m_i[i] = -1e30f;
        l_i[i] = 0.0f;
#pragma unroll
        for (int j = 0; j < 4; j++) accO[i][j] = 0.0f;
    }

    for (int kt = 0; kt <= qt; kt++) {
        const int kbase = kt * BKT;
        __syncthreads();
        for (int i = tid; i < BKT * (DD / 4); i += 256) {
            int row = i >> 4;
            int c4 = (i & 15) * 4;
            float4 k4 = *(const float4*)&Kp[((size_t)(b * SS + kbase + row)) * EE + head_off + c4];
            *(float4*)&Ks[row * KS_STRIDE + c4] = k4;
            float4 v4 = *(const float4*)&Vp[((size_t)(b * SS + kbase + row)) * EE + head_off + c4];
            *(float4*)&Vs[row * DD + c4] = v4;
        }
        __syncthreads();

        float s[4][4];
#pragma unroll
        for (int i = 0; i < 4; i++)
#pragma unroll
            for (int j = 0; j < 4; j++) s[i][j] = 0.0f;

#pragma unroll
        for (int d0 = 0; d0 < DD; d0 += 4) {
            float4 qv[4], kv[4];
#pragma unroll
            for (int i = 0; i < 4; i++) qv[i] = *(float4*)&Qs[(ty * 4 + i) * DD + d0];
#pragma unroll
            for (int j = 0; j < 4; j++) kv[j] = *(float4*)&Ks[(tx * 4 + j) * KS_STRIDE + d0];
#pragma unroll
            for (int i = 0; i < 4; i++)
#pragma unroll
                for (int j = 0; j < 4; j++) {
                    s[i][j] = fmaf(qv[i].x, kv[j].x, s[i][j]);
                    s[i][j] = fmaf(qv[i].y, kv[j].y, s[i][j]);
                    s[i][j] = fmaf(qv[i].z, kv[j].z, s[i][j]);
                    s[i][j] = fmaf(qv[i].w, kv[j].w, s[i][j]);
                }
        }

        if (kt == qt) {
#pragma unroll
            for (int i = 0; i < 4; i++) {
                const int qrow = ty * 4 + i;
#pragma unroll
                for (int j = 0; j < 4; j++) {
                    if (tx * 4 + j > qrow) s[i][j] = -1e30f;
                }
            }
        }

        float alpha[4], ps[4], newm[4];
#pragma unroll
        for (int i = 0; i < 4; i++) {
            float mt = fmaxf(fmaxf(s[i][0], s[i][1]), fmaxf(s[i][2], s[i][3]));
#pragma unroll
            for (int off = 1; off < 16; off <<= 1)
                mt = fmaxf(mt, __shfl_xor_sync(0xffffffffu, mt, off));
            newm[i] = fmaxf(m_i[i], mt);
            alpha[i] = __expf(m_i[i] - newm[i]);
            float sum = 0.0f;
#pragma unroll
            for (int j = 0; j < 4; j++) {
                s[i][j] = __expf(s[i][j] - newm[i]);
                sum += s[i][j];
            }
#pragma unroll
            for (int off = 1; off < 16; off <<= 1)
                sum += __shfl_xor_sync(0xffffffffu, sum, off);
            ps[i] = sum;
        }

        __syncthreads();
#pragma unroll
        for (int i = 0; i < 4; i++) {
            m_i[i] = newm[i];
            l_i[i] = l_i[i] * alpha[i] + ps[i];
#pragma unroll
            for (int j = 0; j < 4; j++) accO[i][j] *= alpha[i];
            float4 p4 = make_float4(s[i][0], s[i][1], s[i][2], s[i][3]);
            *(float4*)&Ks[(ty * 4 + i) * KS_STRIDE + tx * 4] = p4;
        }
        __syncthreads();

#pragma unroll
        for (int k0 = 0; k0 < BKT; k0 += 4) {
            float4 pv[4], vv[4];
#pragma unroll
            for (int i = 0; i < 4; i++) pv[i] = *(float4*)&Ks[(ty * 4 + i) * KS_STRIDE + k0];
#pragma unroll
            for (int kk = 0; kk < 4; kk++) vv[kk] = *(float4*)&Vs[(k0 + kk) * DD + tx * 4];
#pragma unroll
            for (int i = 0; i < 4; i++) {
                accO[i][0] = fmaf(pv[i].x, vv[0].x, accO[i][0]);
                accO[i][1] = fmaf(pv[i].x, vv[0].y, accO[i][1]);
                accO[i][2] = fmaf(pv[i].x, vv[0].z, accO[i][2]);
                accO[i][3] = fmaf(pv[i].x, vv[0].w, accO[i][3]);
                accO[i][0] = fmaf(pv[i].y, vv[1].x, accO[i][0]);
                accO[i][1] = fmaf(pv[i].y, vv[1].y, accO[i][1]);
                accO[i][2] = fmaf(pv[i].y, vv[1].z, accO[i][2]);
                accO[i][3] = fmaf(pv[i].y, vv[1].w, accO[i][3]);
                accO[i][0] = fmaf(pv[i].z, vv[2].x, accO[i][0]);
                accO[i][1] = fmaf(pv[i].z, vv[2].y, accO[i][1]);
                accO[i][2] = fmaf(pv[i].z, vv[2].z, accO[i][2]);
                accO[i][3] = fmaf(pv[i].z, vv[2].w, accO[i][3]);
                accO[i][0] = fmaf(pv[i].w, vv[3].x, accO[i][0]);
                accO[i][1] = fmaf(pv[i].w, vv[3].y, accO[i][1]);
                accO[i][2] = fmaf(pv[i].w, vv[3].z, accO[i][2]);
                accO[i][3] = fmaf(pv[i].w, vv[3].w, accO[i][3]);
            }
        }
    }

#pragma unroll
    for (int i = 0; i < 4; i++) {
        const int qrow = qbase + ty * 4 + i;
        const float inv = 1.0f / l_i[i];
        float4 o = make_float4(accO[i][0] * inv, accO[i][1] * inv,
                               accO[i][2] * inv, accO[i][3] * inv);
        *(float4*)&Out[((size_t)(b * SS + qrow)) * EE + head_off + tx * 4] = o;
    }
}

// ---------------- launch ----------------------------------------------------
extern "C" void kernel_launch(void* const* d_in, const int* in_sizes, int n_in,
                              void* d_out, int out_size)
{
    const float* q  = (const float*)d_in[0];
    const float* k  = (const float*)d_in[1];
    const float* v  = (const float*)d_in[2];
    const float* Wq = (const float*)d_in[3];
    const float* bq = (const float*)d_in[4];
    const float* Wk = (const float*)d_in[5];
    const float* bk = (const float*)d_in[6];
    const float* Wv = (const float*)d_in[7];
    const float* bv = (const float*)d_in[8];
    const float* Wo = (const float*)d_in[9];
    const float* bo = (const float*)d_in[10];
    float* out = (float*)d_out;

    float* qp; cudaGetSymbolAddress((void**)&qp, g_qp);
    float* kp; cudaGetSymbolAddress((void**)&kp, g_kp);
    float* vp; cudaGetSymbolAddress((void**)&vp, g_vp);
    float* at; cudaGetSymbolAddress((void**)&at, g_at);

    cudaFuncSetAttribute(flash_attn_kernel,
                         cudaFuncAttributeMaxDynamicSharedMemorySize,
                         FLASH_SMEM_BYTES);
    cudaFuncSetAttribute(gemm_tf32_mma,
                         cudaFuncAttributeMaxDynamicSharedMemorySize,
                         GEMM_SMEM_B);

    dim3 ggrid(EE / 128, MM / 128);   // (8, 32)
    gemm_tf32_mma<<<ggrid, 256, GEMM_SMEM_B>>>(q, Wq, bq, qp);
    gemm_tf32_mma<<<ggrid, 256, GEMM_SMEM_B>>>(k, Wk, bk, kp);
    gemm_tf32_mma<<<ggrid, 256, GEMM_SMEM_B>>>(v, Wv, bv, vp);

    dim3 fa_grid(SS / BQ, HH, BB);    // (32, 16, 2)
    flash_attn_kernel<<<fa_grid, 256, FLASH_SMEM_BYTES>>>(qp, kp, vp, at);

    gemm_tf32_mma<<<ggrid, 256, GEMM_SMEM_B>>>(at, Wo, bo, out);
}